// round 1
// baseline (speedup 1.0000x reference)
#include <cuda_runtime.h>

#define FULLM 0xffffffffu

constexpr int NQ  = 10;
constexpr int DIN = 256;
constexpr int WPB = 8;   // warps (samples) per block

// ---------------------------------------------------------------------------
// CNOT chain (0,1)(1,2)...(8,9). Qubit q <-> bit q of the amplitude index.
// Bits 0-4 live in-thread (array index j), bits 5-9 live in the lane id.
// ---------------------------------------------------------------------------
__device__ __forceinline__ void cnot_chain(float (&sr)[32], float (&si)[32], int lane)
{
    // (0,1)..(3,4): control & target both thread bits -> pure register permutation
#pragma unroll
    for (int c = 0; c < 4; ++c) {
        const int t = c + 1;
#pragma unroll
        for (int j = 0; j < 32; ++j) {
            if ((((j >> c) & 1) == 1) && (((j >> t) & 1) == 0)) {
                const int j2 = j | (1 << t);
                float tr = sr[j]; sr[j] = sr[j2]; sr[j2] = tr;
                float ti = si[j]; si[j] = si[j2]; si[j2] = ti;
            }
        }
    }
    // (4,5): control = thread bit 4, target = lane bit 0.
    // Only amplitudes with bit4(j)==1 exchange across lane-bit 0.
#pragma unroll
    for (int j = 16; j < 32; ++j) {
        sr[j] = __shfl_xor_sync(FULLM, sr[j], 1);
        si[j] = __shfl_xor_sync(FULLM, si[j], 1);
    }
    // (5,6)..(8,9): both lane bits -> conditional lane permutation via shfl.idx
#pragma unroll
    for (int cb = 0; cb < 4; ++cb) {
        const int tm = 1 << (cb + 1);
        int src = ((lane >> cb) & 1) ? (lane ^ tm) : lane;
#pragma unroll
        for (int j = 0; j < 32; ++j) {
            sr[j] = __shfl_sync(FULLM, sr[j], src);
            si[j] = __shfl_sync(FULLM, si[j], src);
        }
    }
}

__global__ void __launch_bounds__(WPB * 32, 2)
vqc_kernel(const float* __restrict__ x, const float* __restrict__ W,
           const float* __restrict__ b, const float* __restrict__ theta,
           float* __restrict__ out, int batch)
{
    __shared__ float Wt[NQ][DIN];            // transposed W: Wt[q][d]
    __shared__ float bsh[NQ];
    __shared__ float thh[NQ];                // 0.5*theta[0][q][0]  (layer-1 RY half-angle)
    __shared__ float cz1[NQ], sz1[NQ];       // cos/sin of 0.5*theta[0][q][1] (layer-1 RZ)
    __shared__ float cy2[NQ], sy2[NQ];       // layer-2 RY half cos/sin
    __shared__ float cz2[NQ], sz2[NQ];       // layer-2 RZ half cos/sin

    const int tid = threadIdx.x;

    // Stage W transposed (coalesced global read, one-time scattered smem write)
    for (int i = tid; i < DIN * NQ; i += blockDim.x) {
        int d = i / NQ;
        int q = i - d * NQ;
        Wt[q][d] = W[i];
    }
    if (tid < NQ) {
        bsh[tid] = b[tid];
        // theta layout: [NL=2][NQ][2], row-major
        thh[tid] = 0.5f * theta[tid * 2 + 0];
        float hz1 = 0.5f * theta[tid * 2 + 1];
        cz1[tid] = cosf(hz1); sz1[tid] = sinf(hz1);
        float hy2 = 0.5f * theta[(NQ + tid) * 2 + 0];
        cy2[tid] = cosf(hy2); sy2[tid] = sinf(hy2);
        float hz2 = 0.5f * theta[(NQ + tid) * 2 + 1];
        cz2[tid] = cosf(hz2); sz2[tid] = sinf(hz2);
    }
    __syncthreads();

    const int warp = blockIdx.x * WPB + (tid >> 5);
    if (warp >= batch) return;
    const int lane = tid & 31;

    // ---------------- Dense encoder: angles[q] = x[warp] . W[:,q] + b[q] ----
    float ang[NQ];
    {
        float xv[8];
        const float* xr = x + (size_t)warp * DIN;
#pragma unroll
        for (int k = 0; k < 8; ++k) xv[k] = xr[lane + 32 * k];
#pragma unroll
        for (int q = 0; q < NQ; ++q) {
            float acc = 0.f;
#pragma unroll
            for (int k = 0; k < 8; ++k) acc += xv[k] * Wt[q][lane + 32 * k];
#pragma unroll
            for (int o = 16; o; o >>= 1) acc += __shfl_xor_sync(FULLM, acc, o);
            ang[q] = acc + bsh[q];
        }
    }

    // ---------------- Initial state = product of per-qubit 2-vectors --------
    // Per qubit: RZ(t1) RY(t0) RY(a) |0> = ( cos(h)*e^{-i hz}, sin(h)*e^{+i hz} )
    // with h = 0.5*(a + t0), hz = 0.5*t1.
    // Lane factor over qubits 5..9 (lane bits):
    float lfr = 1.f, lfi = 0.f;
#pragma unroll
    for (int qb = 0; qb < 5; ++qb) {
        const int q = 5 + qb;
        float h = 0.5f * ang[q] + thh[q];
        float sn, c;
        __sincosf(h, &sn, &c);
        float cz = cz1[q], sz = sz1[q];
        int bit = (lane >> qb) & 1;
        float amp = bit ? sn : c;
        float ph  = bit ? sz : -sz;
        float vr = amp * cz;
        float vi = amp * ph;
        float nr = lfr * vr - lfi * vi;
        float ni = lfr * vi + lfi * vr;
        lfr = nr; lfi = ni;
    }
    // In-thread qubits 0..4: per-qubit 2-vectors
    float u0r[5], u0i[5], u1r[5], u1i[5];
#pragma unroll
    for (int q = 0; q < 5; ++q) {
        float h = 0.5f * ang[q] + thh[q];
        float sn, c;
        __sincosf(h, &sn, &c);
        float cz = cz1[q], sz = sz1[q];
        u0r[q] = c * cz;  u0i[q] = -c * sz;
        u1r[q] = sn * cz; u1i[q] = sn * sz;
    }
    // Build 32 in-thread amplitudes by progressive doubling
    float sr[32], si[32];
    sr[0] = lfr; si[0] = lfi;
#pragma unroll
    for (int q = 0; q < 5; ++q) {
        const int n = 1 << q;
#pragma unroll
        for (int j = n - 1; j >= 0; --j) {
            float xr0 = sr[j], xi0 = si[j];
            sr[j + n] = xr0 * u1r[q] - xi0 * u1i[q];
            si[j + n] = xr0 * u1i[q] + xi0 * u1r[q];
            sr[j]     = xr0 * u0r[q] - xi0 * u0i[q];
            si[j]     = xr0 * u0i[q] + xi0 * u0r[q];
        }
    }

    // ---------------- Layer-1 entanglers ------------------------------------
    cnot_chain(sr, si, lane);

    // ---------------- Layer-2 rotations: RY(t0) then RZ(t1) per qubit -------
    // Thread qubits 0..4:
#pragma unroll
    for (int q = 0; q < 5; ++q) {
        float c = cy2[q], s = sy2[q], cz = cz2[q], sz = sz2[q];
#pragma unroll
        for (int j = 0; j < 32; ++j) {
            if (((j >> q) & 1) == 0) {
                const int j2 = j | (1 << q);
                float a0r = sr[j],  a0i = si[j];
                float a1r = sr[j2], a1i = si[j2];
                float n0r = c * a0r - s * a1r, n0i = c * a0i - s * a1i;
                float n1r = s * a0r + c * a1r, n1i = s * a0i + c * a1i;
                // RZ: bit0 -> (cz,-sz), bit1 -> (cz,+sz)
                sr[j]  = n0r * cz + n0i * sz;  si[j]  = n0i * cz - n0r * sz;
                sr[j2] = n1r * cz - n1i * sz;  si[j2] = n1i * cz + n1r * sz;
            }
        }
    }
    // Lane qubits 5..9:
#pragma unroll
    for (int qb = 0; qb < 5; ++qb) {
        const int q = 5 + qb;
        float c = cy2[q], s = sy2[q], cz = cz2[q], sz = sz2[q];
        int bit = (lane >> qb) & 1;
        float ss = bit ? s  : -s;   // RY: new = c*mine + ss*other
        float e  = bit ? sz : -sz;  // RZ phase sign
#pragma unroll
        for (int j = 0; j < 32; ++j) {
            float orr = __shfl_xor_sync(FULLM, sr[j], 1 << qb);
            float oii = __shfl_xor_sync(FULLM, si[j], 1 << qb);
            float nr = c * sr[j] + ss * orr;
            float ni = c * si[j] + ss * oii;
            sr[j] = nr * cz - ni * e;
            si[j] = ni * cz + nr * e;
        }
    }

    // ---------------- Layer-2 entanglers ------------------------------------
    cnot_chain(sr, si, lane);

    // ---------------- Measurement: mean_q <Z_q> -----------------------------
    // expv = sum_idx |amp|^2 * (NQ - 2*popc(idx)) / NQ ;  out = expv (MIN=-1,MAX=1)
    const float wl = 0.1f * (float)(NQ - 2 * __popc(lane));
    float acc = 0.f;
#pragma unroll
    for (int j = 0; j < 32; ++j) {
        float w = wl - 0.2f * (float)__popc((unsigned)j);  // popc(j): compile-time
        acc += (sr[j] * sr[j] + si[j] * si[j]) * w;
    }
#pragma unroll
    for (int o = 16; o; o >>= 1) acc += __shfl_xor_sync(FULLM, acc, o);
    if (lane == 0) out[warp] = acc;
}

extern "C" void kernel_launch(void* const* d_in, const int* in_sizes, int n_in,
                              void* d_out, int out_size)
{
    // Map inputs by element count (metadata order: x, W, b, theta) —
    // size-based mapping is robust either way.
    const float* x  = nullptr;
    const float* W  = nullptr;
    const float* b  = nullptr;
    const float* th = nullptr;
    for (int i = 0; i < n_in; ++i) {
        int sz = in_sizes[i];
        if      (sz == 4096 * 256) x  = (const float*)d_in[i];
        else if (sz == 256 * 10)   W  = (const float*)d_in[i];
        else if (sz == 10)         b  = (const float*)d_in[i];
        else if (sz == 2 * 10 * 2) th = (const float*)d_in[i];
    }
    // Fallback to positional if sizes ever change shape
    if (!x)  x  = (const float*)d_in[0];
    if (!W)  W  = (const float*)d_in[1];
    if (!b)  b  = (const float*)d_in[2];
    if (!th) th = (const float*)d_in[3];

    int batch = out_size;  // [B,1] float32 output
    int blocks = (batch + WPB - 1) / WPB;
    vqc_kernel<<<blocks, WPB * 32>>>(x, W, b, th, (float*)d_out, batch);
}

// round 2
// speedup vs baseline: 2.1097x; 2.1097x over previous
#include <cuda_runtime.h>

#define FULLM 0xffffffffu

constexpr int NQ  = 10;
constexpr int DIN = 256;
constexpr int WPB = 8;   // warps (samples) per block

// compile-time parity helpers
__host__ __device__ constexpr int par(unsigned v) {
    int p = 0;
    while (v) { p ^= (v & 1); v >>= 1; }
    return p;
}

__global__ void __launch_bounds__(WPB * 32, 2)
vqc_kernel(const float* __restrict__ x, const float* __restrict__ W,
           const float* __restrict__ b, const float* __restrict__ theta,
           float* __restrict__ out, int batch)
{
    __shared__ float Wt[NQ][DIN];            // transposed W: Wt[q][d]
    __shared__ float bsh[NQ];
    __shared__ float thh[NQ];                // 0.5*theta[0][q][0]  (layer-1 RY half-angle)
    __shared__ float cz1[NQ], sz1[NQ];       // layer-1 RZ half cos/sin
    __shared__ float cy2[NQ], sy2[NQ];       // layer-2 RY half cos/sin (RZ2 dropped: diagonal)

    const int tid = threadIdx.x;

    for (int i = tid; i < DIN * NQ; i += blockDim.x) {
        int d = i / NQ;
        int q = i - d * NQ;
        Wt[q][d] = W[i];
    }
    if (tid < NQ) {
        bsh[tid] = b[tid];
        thh[tid] = 0.5f * theta[tid * 2 + 0];
        float hz1 = 0.5f * theta[tid * 2 + 1];
        cz1[tid] = cosf(hz1); sz1[tid] = sinf(hz1);
        float hy2 = 0.5f * theta[(NQ + tid) * 2 + 0];
        cy2[tid] = cosf(hy2); sy2[tid] = sinf(hy2);
    }
    __syncthreads();

    const int warp = blockIdx.x * WPB + (tid >> 5);
    if (warp >= batch) return;
    const int lane = tid & 31;

    // ---------------- Dense encoder: angles[q] = x[warp] . W[:,q] + b[q] ----
    float ang[NQ];
    {
        float xv[8];
        const float* xr = x + (size_t)warp * DIN;
#pragma unroll
        for (int k = 0; k < 8; ++k) xv[k] = xr[lane + 32 * k];
#pragma unroll
        for (int q = 0; q < NQ; ++q) {
            float acc = 0.f;
#pragma unroll
            for (int k = 0; k < 8; ++k) acc += xv[k] * Wt[q][lane + 32 * k];
#pragma unroll
            for (int o = 16; o; o >>= 1) acc += __shfl_xor_sync(FULLM, acc, o);
            ang[q] = acc + bsh[q];
        }
    }

    // ---------------- Initial product state (encoding RY + L1 RY + L1 RZ) ---
    // Per qubit: ( cos(h) e^{-i hz}, sin(h) e^{+i hz} ), h = 0.5*ang + 0.5*t0.
    float lfr = 1.f, lfi = 0.f;
#pragma unroll
    for (int qb = 0; qb < 5; ++qb) {
        const int q = 5 + qb;
        float h = 0.5f * ang[q] + thh[q];
        float sn, c;
        __sincosf(h, &sn, &c);
        float cz = cz1[q], sz = sz1[q];
        int bit = (lane >> qb) & 1;
        float amp = bit ? sn : c;
        float ph  = bit ? sz : -sz;
        float vr = amp * cz;
        float vi = amp * ph;
        float nr = lfr * vr - lfi * vi;
        float ni = lfr * vi + lfi * vr;
        lfr = nr; lfi = ni;
    }
    float u0r[5], u0i[5], u1r[5], u1i[5];
#pragma unroll
    for (int q = 0; q < 5; ++q) {
        float h = 0.5f * ang[q] + thh[q];
        float sn, c;
        __sincosf(h, &sn, &c);
        float cz = cz1[q], sz = sz1[q];
        u0r[q] = c * cz;  u0i[q] = -c * sz;
        u1r[q] = sn * cz; u1i[q] = sn * sz;
    }
    float sr[32], si[32];
    sr[0] = lfr; si[0] = lfi;
#pragma unroll
    for (int q = 0; q < 5; ++q) {
        const int n = 1 << q;
#pragma unroll
        for (int j = n - 1; j >= 0; --j) {
            float xr0 = sr[j], xi0 = si[j];
            sr[j + n] = xr0 * u1r[q] - xi0 * u1i[q];
            si[j + n] = xr0 * u1i[q] + xi0 * u1r[q];
            sr[j]     = xr0 * u0r[q] - xi0 * u0i[q];
            si[j]     = xr0 * u0i[q] + xi0 * u0r[q];
        }
    }

    // ---------------- CNOT chain #1: pure relabeling, A = L (zero data movement)
    //
    // Layer-2 RY on logical qubit q now pairs PHYSICAL bits {q, q+1} (q<9),
    // and bit {9} for q=9. Logical-bit value at slot s: parity(s & (2^{q+1}-1)).

    // q = 0..3 : both pairing bits in-thread
#pragma unroll
    for (int q = 0; q < 4; ++q) {
        const float c = cy2[q], s = sy2[q];
        const int m = (1 << q) | (1 << (q + 1));
        const unsigned lowmask = (1u << (q + 1)) - 1u;
#pragma unroll
        for (int j = 0; j < 32; ++j) {
            if (par((unsigned)j & lowmask) == 0) {       // b(j)=0 side; partner has b=1
                const int j2 = j ^ m;
                float a0r = sr[j],  a0i = si[j];
                float a1r = sr[j2], a1i = si[j2];
                sr[j]  = c * a0r - s * a1r;  si[j]  = c * a0i - s * a1i;
                sr[j2] = s * a0r + c * a1r;  si[j2] = s * a0i + c * a1i;
            }
        }
    }

    // q = 4 : pairing bits {4 (thread), 5 (lane bit 0)}; b = parity(j) (j-only)
    {
        const float c = cy2[4], s = sy2[4];
#pragma unroll
        for (int j = 0; j < 16; ++j) {
            const int j2 = j | 16;
            float o0r = __shfl_xor_sync(FULLM, sr[j2], 1);  // partner of slot j
            float o0i = __shfl_xor_sync(FULLM, si[j2], 1);
            float o1r = __shfl_xor_sync(FULLM, sr[j],  1);  // partner of slot j2
            float o1i = __shfl_xor_sync(FULLM, si[j],  1);
            // b(j) = parity(j) (bit4=0 here), b(j2) = parity(j) ^ 1
            const float sj  = par((unsigned)j) ? s : -s;
            const float sj2 = -sj;
            sr[j]  = c * sr[j]  + sj  * o0r;  si[j]  = c * si[j]  + sj  * o0i;
            sr[j2] = c * sr[j2] + sj2 * o1r;  si[j2] = c * si[j2] + sj2 * o1i;
        }
    }

    // q = 5..8 : pairing bits {q, q+1} = lane bits {q-5, q-4}; b = parity(j) ^ parity(l & ((1<<(q-4))-1))
#pragma unroll
    for (int q = 5; q < 9; ++q) {
        const float c = cy2[q], s = sy2[q];
        const int ml = (1 << (q - 5)) | (1 << (q - 4));
        const int pl = __popc(lane & ((1 << (q - 4)) - 1)) & 1;
        const float sl = pl ? s : -s;   // sign if parity(j)==0 is -sl? see below
#pragma unroll
        for (int j = 0; j < 32; ++j) {
            float orr = __shfl_xor_sync(FULLM, sr[j], ml);
            float oii = __shfl_xor_sync(FULLM, si[j], ml);
            // b = parity(j) ^ pl ; sign = b ? +s : -s  = (parity(j) ? -1 : +1) * (pl ? +s : -s)... 
            // pl=1,pj=0 -> b=1 -> +s = +sl ; pl=0,pj=0 -> b=0 -> -s = sl(-s) OK sl works for pj=0.
            // pj=1 flips: use -sl.
            const float se = par((unsigned)j) ? -sl : sl;
            sr[j] = c * sr[j] + se * orr;
            si[j] = c * si[j] + se * oii;
        }
    }

    // q = 9 : pairing bit {9} = lane bit 4; b = parity(j) ^ parity(l & 0xF)... full mask bits 0..9:
    {
        const float c = cy2[9], s = sy2[9];
        const int pl = __popc(lane & 0xF) & 1;   // lane bits 0..3 (bit 9 itself is the pairing bit; include it? mask = bits 0..9 -> lane bits 0..4)
        const int pl4 = (lane >> 4) & 1;
        const int plf = pl ^ pl4;                // parity(l & 0x1F)
        const float sl = plf ? s : -s;
#pragma unroll
        for (int j = 0; j < 32; ++j) {
            float orr = __shfl_xor_sync(FULLM, sr[j], 16);
            float oii = __shfl_xor_sync(FULLM, si[j], 16);
            const float se = par((unsigned)j) ? -sl : sl;
            sr[j] = c * sr[j] + se * orr;
            si[j] = c * si[j] + se * oii;
        }
    }

    // (Layer-2 RZ dropped: diagonal gate followed only by a permutation + |.|^2.)
    // ---------------- CNOT chain #2: relabeling only, A = L^2 ----------------
    // Measurement: n_t = parity(s & row_t(L^2)), row_t = bits {t, t-2, t-4, ...}
    // popc(n) = Jlow(j) + popc(Lbits ^ Jhi(j)), weight = 1 - 0.2*popc(n).
    const int pl5 = lane & 1;
    const int pl6 = (lane >> 1) & 1;
    const int pl7 = __popc(lane & 0x05) & 1;
    const int pl8 = __popc(lane & 0x0A) & 1;
    const int pl9 = __popc(lane & 0x15) & 1;
    const int Lbits = pl5 | (pl6 << 1) | (pl7 << 2) | (pl8 << 3) | (pl9 << 4);

    float acc = 0.f;
#pragma unroll
    for (int j = 0; j < 32; ++j) {
        const int pj0 = j & 1;
        const int pj1 = (j >> 1) & 1;
        const int pj2 = par((unsigned)j & 0x05u);
        const int pj3 = par((unsigned)j & 0x0Au);
        const int pj4 = par((unsigned)j & 0x15u);
        const int Jlow = pj0 + pj1 + pj2 + pj3 + pj4;
        const int pA = par((unsigned)j & 0x0Au);   // t = 5,7,9
        const int pB = par((unsigned)j & 0x15u);   // t = 6,8
        const int Jhi = pA * 0x15 + pB * 0x0A;
        const int pn = Jlow + __popc(Lbits ^ Jhi);
        const float w = 1.0f - 0.2f * (float)pn;
        acc += (sr[j] * sr[j] + si[j] * si[j]) * w;
    }
#pragma unroll
    for (int o = 16; o; o >>= 1) acc += __shfl_xor_sync(FULLM, acc, o);
    if (lane == 0) out[warp] = acc;
}

extern "C" void kernel_launch(void* const* d_in, const int* in_sizes, int n_in,
                              void* d_out, int out_size)
{
    const float* x  = nullptr;
    const float* W  = nullptr;
    const float* b  = nullptr;
    const float* th = nullptr;
    for (int i = 0; i < n_in; ++i) {
        int sz = in_sizes[i];
        if      (sz == 4096 * 256) x  = (const float*)d_in[i];
        else if (sz == 256 * 10)   W  = (const float*)d_in[i];
        else if (sz == 10)         b  = (const float*)d_in[i];
        else if (sz == 2 * 10 * 2) th = (const float*)d_in[i];
    }
    if (!x)  x  = (const float*)d_in[0];
    if (!W)  W  = (const float*)d_in[1];
    if (!b)  b  = (const float*)d_in[2];
    if (!th) th = (const float*)d_in[3];

    int batch = out_size;
    int blocks = (batch + WPB - 1) / WPB;
    vqc_kernel<<<blocks, WPB * 32>>>(x, W, b, th, (float*)d_out, batch);
}